// round 13
// baseline (speedup 1.0000x reference)
#include <cuda_runtime.h>
#include <cuda_bf16.h>

#define NN    20000
#define EE    320000
#define BB    128
#define DIN   64
#define HH    2
#define CC    64
#define LL    2
#define SLOPE 0.2f
#define EPSBN 1e-5f
#define BN_BLOCKS 100

// PDL: wait for predecessor grid's writes to be visible.
#define GDS() cudaGridDependencySynchronize()

// ---------------- scratch (device globals; no allocation) ----------------
__device__ float g_xl[NN * 128];            // [N][128] node features (both heads)
__device__ float g_al[NN * HH];
__device__ float g_ar[NN * HH];
__device__ float g_pe[LL * EE * HH];        // ae dot + ins term, both layers
__device__ float g_h[NN * DIN];             // hidden state between layers (pre-BN)
__device__ float g_wa[LL * 3 * 128 * HH];   // folded att vectors [l][{al,ar,ae}][k][h]
__device__ float g_ins_xl[LL * BB * 128];   // ins @ W_l_bottom
__device__ float g_ins_a[LL * 3 * BB * HH]; // ins @ w_{al,ar,ae}_bottom
__device__ int   g_cnt[NN];                 // in-degree histogram (zeroed by scan each call)
__device__ int   g_start[NN + 1];           // CSR row starts
__device__ int   g_cur[NN];                 // placement cursors
__device__ int   g_csr[EE];                 // edge ids grouped by dst (sorted per bucket)
__device__ float g_bnp[BN_BLOCKS * 64];
__device__ float g_bnp2[BN_BLOCKS * 64];
__device__ float g_mu[64];
__device__ float g_scale[64];               // gamma * rsqrt(var + eps)

// ---------------- prep 1: fold att vectors through W ----------------
__global__ void prep_weights(const float* __restrict__ Wl, const float* __restrict__ We,
                             const float* __restrict__ attl, const float* __restrict__ attr_,
                             const float* __restrict__ atte) {
    int idx = blockIdx.x * blockDim.x + threadIdx.x;
    if (idx >= LL * 3 * 128 * HH) return;
    int l  = idx / (3 * 128 * HH);
    int r  = idx % (3 * 128 * HH);
    int t  = r / (128 * HH);
    int r2 = r % (128 * HH);
    int k  = r2 / HH;
    int h  = r2 % HH;
    const float* W   = (t == 2) ? We : Wl;
    const float* att = (t == 0) ? attl : (t == 1) ? attr_ : atte;
    float acc = 0.f;
#pragma unroll 8
    for (int c = 0; c < CC; c++)
        acc += W[l * 128 * 128 + k * 128 + h * CC + c] * att[l * HH * CC + h * CC + c];
    g_wa[((l * 3 + t) * 128 + k) * HH + h] = acc;
}

// ---------------- prep 2: per-graph instruction terms + dst histogram ----------------
__global__ void prep_ins(const float* __restrict__ ins, const float* __restrict__ Wl,
                         const int* __restrict__ ei) {
    GDS();
    int idx = blockIdx.x * blockDim.x + threadIdx.x;
    const int NXL = LL * BB * 128;
    if (idx < NXL) {
        int l = idx / (BB * 128);
        int r = idx % (BB * 128);
        int b = r / 128;
        int m = r % 128;
        float acc = 0.f;
#pragma unroll 8
        for (int k = 0; k < DIN; k++)
            acc += ins[(l * BB + b) * DIN + k] * Wl[l * 128 * 128 + (64 + k) * 128 + m];
        g_ins_xl[(l * BB + b) * 128 + m] = acc;
    } else if (idx < NXL + LL * 3 * BB * HH) {
        int j  = idx - NXL;
        int l  = j / (3 * BB * HH);
        int r  = j % (3 * BB * HH);
        int t  = r / (BB * HH);
        int r2 = r % (BB * HH);
        int b  = r2 / HH;
        int h  = r2 % HH;
        float acc = 0.f;
#pragma unroll 8
        for (int k = 0; k < DIN; k++)
            acc += ins[(l * BB + b) * DIN + k] * g_wa[((l * 3 + t) * 128 + 64 + k) * HH + h];
        g_ins_a[((l * 3 + t) * BB + b) * HH + h] = acc;
    }
    if (idx < EE) atomicAdd(&g_cnt[ei[EE + idx]], 1);
}

// ---------------- scan: single block; exclusive prefix; writes start/cur; zeroes cnt ----------------
__global__ __launch_bounds__(1024) void scan_kernel() {
    GDS();
    __shared__ int wsum[32];
    int t = threadIdx.x;
    int lane = t & 31, wid = t >> 5;
    int base = t * 20;
    int vals[20];
    int s = 0;
#pragma unroll
    for (int i = 0; i < 20; i++) {
        int n = base + i;
        int c = (n < NN) ? g_cnt[n] : 0;
        vals[i] = s;                // exclusive local prefix
        s += c;
    }
    int inc = s;
#pragma unroll
    for (int o = 1; o < 32; o <<= 1) {
        int u = __shfl_up_sync(0xffffffffu, inc, o);
        if (lane >= o) inc += u;
    }
    int wexcl = inc - s;
    if (lane == 31) wsum[wid] = inc;
    __syncthreads();
    if (wid == 0) {
        int v = wsum[lane];
        int inc2 = v;
#pragma unroll
        for (int o = 1; o < 32; o <<= 1) {
            int u = __shfl_up_sync(0xffffffffu, inc2, o);
            if (lane >= o) inc2 += u;
        }
        wsum[lane] = inc2 - v;      // exclusive warp offsets
    }
    __syncthreads();
    int boff = wsum[wid] + wexcl;
#pragma unroll
    for (int i = 0; i < 20; i++) {
        int n = base + i;
        if (n < NN) {
            int st = boff + vals[i];
            g_start[n] = st;
            g_cur[n] = st;
            g_cnt[n] = 0;           // ready for next call
        }
    }
    if (t == 0) g_start[NN] = EE;
}

__global__ void place_kernel(const int* __restrict__ ei) {
    GDS();
    int e = blockIdx.x * blockDim.x + threadIdx.x;
    if (e >= EE) return;
    int d = ei[EE + e];
    int pos = atomicAdd(&g_cur[d], 1);
    g_csr[pos] = e;
}

// ---------------- canonicalize bucket order: warp rank sort ----------------
__global__ __launch_bounds__(256) void sort_kernel() {
    GDS();
    int warp = threadIdx.x >> 5, lane = threadIdx.x & 31;
    int n = blockIdx.x * 8 + warp;
    if (n >= NN) return;
    int s0 = g_start[n], s1 = g_start[n + 1];
    int d = s1 - s0;
    if (d <= 1) return;
    if (d <= 32) {
        int v = (lane < d) ? g_csr[s0 + lane] : 0x7fffffff;
        int rank = 0;
#pragma unroll
        for (int j = 0; j < 32; j++) {
            int u = __shfl_sync(0xffffffffu, v, j);
            rank += (u < v);
        }
        __syncwarp();
        if (lane < d) g_csr[s0 + rank] = v;
    } else if (lane == 0) {
        for (int i = s0 + 1; i < s1; i++) {
            int v = g_csr[i];
            int j = i - 1;
            while (j >= s0 && g_csr[j] > v) { g_csr[j + 1] = g_csr[j]; j--; }
            g_csr[j + 1] = v;
        }
    }
}

// ---------------- edge precompute (ONCE): ae dots + ins terms, both layers ----------------
__global__ __launch_bounds__(256) void edge_pre(
    const int* __restrict__ ei, const float* __restrict__ ea,
    const int* __restrict__ batch) {
    GDS();
    int warp = threadIdx.x >> 5, lane = threadIdx.x & 31;
    int e = blockIdx.x * 8 + warp;
    float ea0 = ea[e * 64 + lane];
    float ea1 = ea[e * 64 + 32 + lane];
    float p[LL][HH];
#pragma unroll
    for (int l = 0; l < LL; l++) {
        const float* w = &g_wa[((l * 3 + 2) * 128) * HH];
#pragma unroll
        for (int h = 0; h < HH; h++)
            p[l][h] = ea0 * w[lane * 2 + h] + ea1 * w[(lane + 32) * 2 + h];
    }
#pragma unroll
    for (int off = 16; off; off >>= 1)
#pragma unroll
        for (int l = 0; l < LL; l++)
#pragma unroll
            for (int h = 0; h < HH; h++)
                p[l][h] += __shfl_xor_sync(0xffffffffu, p[l][h], off);
    if (lane == 0) {
        int s = ei[e];
        int b = batch[s];
#pragma unroll
        for (int l = 0; l < LL; l++) {
            float2 v;
            v.x = p[l][0] + g_ins_a[((l * 3 + 2) * BB + b) * HH + 0];
            v.y = p[l][1] + g_ins_a[((l * 3 + 2) * BB + b) * HH + 1];
            *(float2*)&g_pe[(l * EE + e) * 2] = v;
        }
    }
}

// ---------------- node kernel: xl, al, ar (optional fused BN+relu on input) ----------------
__global__ __launch_bounds__(128) void node_kernel(
    const float* __restrict__ x, const int* __restrict__ batch,
    const float* __restrict__ Wl, const float* __restrict__ beta,
    int l, int use_x, int bn_in) {
    GDS();
    __shared__ __align__(16) float hs[64][16];   // [k][n]
    __shared__ int bsm[16];
    const float* hin = use_x ? x : g_h;
    int node0 = blockIdx.x * 16;
    int t = threadIdx.x;
#pragma unroll
    for (int i = t; i < 16 * 64; i += 128) {
        int n = i >> 6, k = i & 63;
        float v = hin[(node0 + n) * DIN + k];
        if (bn_in) {
            v = (v - g_mu[k]) * g_scale[k] + beta[k];
            v = v > 0.f ? v : 0.f;
        }
        hs[k][n] = v;
    }
    if (t < 16) bsm[t] = batch[node0 + t];
    __syncthreads();

    int m = t;  // output column 0..127
    float acc[16];
#pragma unroll
    for (int n = 0; n < 16; n++)
        acc[n] = g_ins_xl[(l * BB + bsm[n]) * 128 + m];

    const float* Wtop = Wl + l * 128 * 128;
#pragma unroll 4
    for (int k = 0; k < 64; k++) {
        float w = Wtop[k * 128 + m];
        float4 a = *(const float4*)&hs[k][0];
        float4 b = *(const float4*)&hs[k][4];
        float4 c = *(const float4*)&hs[k][8];
        float4 d = *(const float4*)&hs[k][12];
        acc[0]  += a.x * w; acc[1]  += a.y * w; acc[2]  += a.z * w; acc[3]  += a.w * w;
        acc[4]  += b.x * w; acc[5]  += b.y * w; acc[6]  += b.z * w; acc[7]  += b.w * w;
        acc[8]  += c.x * w; acc[9]  += c.y * w; acc[10] += c.z * w; acc[11] += c.w * w;
        acc[12] += d.x * w; acc[13] += d.y * w; acc[14] += d.z * w; acc[15] += d.w * w;
    }
#pragma unroll
    for (int n = 0; n < 16; n++)
        g_xl[(node0 + n) * 128 + m] = acc[n];

    if (t < 64) {
        int n  = t >> 2;
        int q  = t & 3;
        int ta = q >> 1;
        int hh = q & 1;
        float a2 = 0.f;
        const float* w = &g_wa[((l * 3 + ta) * 128) * HH + hh];
#pragma unroll 8
        for (int k = 0; k < 64; k++)
            a2 += hs[k][n] * w[k * HH];
        a2 += g_ins_a[((l * 3 + ta) * BB + bsm[n]) * HH + hh];
        float* dst = (ta == 0) ? g_al : g_ar;
        dst[(node0 + n) * HH + hh] = a2;
    }
}

// =================================================================
// gather: 256 thr = 8 warps = 8 nodes/block; fused logit+exp+softmax+agg
// (byte-identical hot loops to the measured-best R6 kernel)
// =================================================================
__global__ __launch_bounds__(256) void gather_kernel(
    const float* __restrict__ x, const float* __restrict__ bias,
    const float* __restrict__ beta, float* __restrict__ dout,
    const int* __restrict__ ei, int l, int use_x, int bn_in, int do_bn_out) {
    GDS();
    int warp = threadIdx.x >> 5, lane = threadIdx.x & 31;
    int n = blockIdx.x * 8 + warp;
    const float* hin = use_x ? x : g_h;
    float* hout = do_bn_out ? g_h : dout;
    int s0 = g_start[n], s1 = g_start[n + 1];
    float2 arn = *(const float2*)&g_ar[n * 2];

    // chunk 0 (covers all edges when deg <= 32): per-lane logit -> exp
    int i = s0 + lane;
    int src = 0;
    float ex0 = 0.f, ex1 = 0.f;
    if (i < s1) {
        int e = g_csr[i];
        src = ei[e];
        float2 pe = *(const float2*)&g_pe[(l * EE + e) * 2];
        float2 al2 = *(const float2*)&g_al[src * 2];
        float a0 = pe.x + al2.x + arn.x;
        float a1 = pe.y + al2.y + arn.y;
        a0 = a0 > 0.f ? a0 : SLOPE * a0;
        a1 = a1 > 0.f ? a1 : SLOPE * a1;
        ex0 = __expf(a0);
        ex1 = __expf(a1);
    }
    float ss0 = ex0, ss1 = ex1;
    for (int base = s0 + 32; base < s1; base += 32) {   // rare (deg > 32)
        int j = base + lane;
        if (j < s1) {
            int e = g_csr[j];
            int sj = ei[e];
            float2 pe = *(const float2*)&g_pe[(l * EE + e) * 2];
            float2 al2 = *(const float2*)&g_al[sj * 2];
            float a0 = pe.x + al2.x + arn.x;
            float a1 = pe.y + al2.y + arn.y;
            a0 = a0 > 0.f ? a0 : SLOPE * a0;
            a1 = a1 > 0.f ? a1 : SLOPE * a1;
            ss0 += __expf(a0);
            ss1 += __expf(a1);
        }
    }
#pragma unroll
    for (int off = 16; off; off >>= 1) {
        ss0 += __shfl_xor_sync(0xffffffffu, ss0, off);
        ss1 += __shfl_xor_sync(0xffffffffu, ss1, off);
    }
    float inv0 = 0.5f / (ss0 + 1e-16f);
    float inv1 = 0.5f / (ss1 + 1e-16f);

    // accumulate: lane reads one float4 of the 128-float source row.
    // lanes 0-15 cover head0 (cols 0..63), lanes 16-31 head1 (cols 64..127).
    float4 acc = make_float4(0.f, 0.f, 0.f, 0.f);
    bool head0 = (lane < 16);
    int dc = s1 - s0; if (dc > 32) dc = 32;
    for (int k = 0; k < dc; k++) {
        float w0 = __shfl_sync(0xffffffffu, ex0, k) * inv0;
        float w1 = __shfl_sync(0xffffffffu, ex1, k) * inv1;
        int sj   = __shfl_sync(0xffffffffu, src, k);
        float w = head0 ? w0 : w1;
        float4 v = ((const float4*)(g_xl + sj * 128))[lane];
        acc.x += w * v.x; acc.y += w * v.y; acc.z += w * v.z; acc.w += w * v.w;
    }
    // rare tail: recompute ex per chunk (deterministic), then accumulate
    for (int base = s0 + 32; base < s1; base += 32) {
        int j = base + lane;
        int src2 = 0;
        float e0 = 0.f, e1 = 0.f;
        if (j < s1) {
            int e = g_csr[j];
            src2 = ei[e];
            float2 pe = *(const float2*)&g_pe[(l * EE + e) * 2];
            float2 al2 = *(const float2*)&g_al[src2 * 2];
            float a0 = pe.x + al2.x + arn.x;
            float a1 = pe.y + al2.y + arn.y;
            a0 = a0 > 0.f ? a0 : SLOPE * a0;
            a1 = a1 > 0.f ? a1 : SLOPE * a1;
            e0 = __expf(a0);
            e1 = __expf(a1);
        }
        int cnt = s1 - base; if (cnt > 32) cnt = 32;
        for (int k = 0; k < cnt; k++) {
            float w0 = __shfl_sync(0xffffffffu, e0, k) * inv0;
            float w1 = __shfl_sync(0xffffffffu, e1, k) * inv1;
            int sj   = __shfl_sync(0xffffffffu, src2, k);
            float w = head0 ? w0 : w1;
            float4 v = ((const float4*)(g_xl + sj * 128))[lane];
            acc.x += w * v.x; acc.y += w * v.y; acc.z += w * v.z; acc.w += w * v.w;
        }
    }

    // head mean: lane L (head0 part) + lane L+16 (head1 part) -> channels 4L..4L+3
    acc.x += __shfl_down_sync(0xffffffffu, acc.x, 16);
    acc.y += __shfl_down_sync(0xffffffffu, acc.y, 16);
    acc.z += __shfl_down_sync(0xffffffffu, acc.z, 16);
    acc.w += __shfl_down_sync(0xffffffffu, acc.w, 16);

    if (lane < 16) {
        float4 h4 = ((const float4*)(hin + n * DIN))[lane];
        if (bn_in) {
            float4 mu = ((const float4*)g_mu)[lane];
            float4 sc = ((const float4*)g_scale)[lane];
            float4 be = ((const float4*)beta)[lane];
            h4.x = (h4.x - mu.x) * sc.x + be.x; h4.x = h4.x > 0.f ? h4.x : 0.f;
            h4.y = (h4.y - mu.y) * sc.y + be.y; h4.y = h4.y > 0.f ? h4.y : 0.f;
            h4.z = (h4.z - mu.z) * sc.z + be.z; h4.z = h4.z > 0.f ? h4.z : 0.f;
            h4.w = (h4.w - mu.w) * sc.w + be.w; h4.w = h4.w > 0.f ? h4.w : 0.f;
        }
        float4 b4 = ((const float4*)(bias + l * CC))[lane];
        float4 o;
        o.x = acc.x + b4.x + h4.x;
        o.y = acc.y + b4.y + h4.y;
        o.z = acc.z + b4.z + h4.z;
        o.w = acc.w + b4.w + h4.w;
        ((float4*)(hout + n * DIN))[lane] = o;
    }
}

// ---------------- BN stats (deterministic two-stage) ----------------
__global__ __launch_bounds__(256) void bn_stats() {
    GDS();
    __shared__ float s1[256], s2m[256];
    int t = threadIdx.x;
    int c = t & 63, slot = t >> 6;
    float su = 0.f, sq = 0.f;
    for (int n = blockIdx.x * 4 + slot; n < NN; n += BN_BLOCKS * 4) {
        float v = g_h[n * DIN + c];
        su += v;
        sq += v * v;
    }
    s1[t] = su; s2m[t] = sq;
    __syncthreads();
    if (t < 64) {
        g_bnp[blockIdx.x * 64 + t]  = s1[t] + s1[t + 64] + s1[t + 128] + s1[t + 192];
        g_bnp2[blockIdx.x * 64 + t] = s2m[t] + s2m[t + 64] + s2m[t + 128] + s2m[t + 192];
    }
}

__global__ void bn_finalize(const float* __restrict__ gamma) {
    GDS();
    int c = threadIdx.x;
    if (c >= 64) return;
    float su = 0.f, sq = 0.f;
    for (int b = 0; b < BN_BLOCKS; b++) {
        su += g_bnp[b * 64 + c];
        sq += g_bnp2[b * 64 + c];
    }
    float mu = su / (float)NN;
    float var = sq / (float)NN - mu * mu;
    g_mu[c] = mu;
    g_scale[c] = gamma[c] * rsqrtf(var + EPSBN);
}

// ---------------- PDL launcher: overlap launch/ramp with predecessor drain ----------------
template <typename F, typename... Args>
static void pdl(F kern, dim3 grid, dim3 block, Args... args) {
    cudaLaunchConfig_t cfg = {};
    cfg.gridDim = grid;
    cfg.blockDim = block;
    cfg.dynamicSmemBytes = 0;
    cfg.stream = 0;
    cudaLaunchAttribute attr;
    attr.id = cudaLaunchAttributeProgrammaticStreamSerialization;
    attr.val.programmaticStreamSerializationAllowed = 1;
    cfg.attrs = &attr;
    cfg.numAttrs = 1;
    if (cudaLaunchKernelEx(&cfg, kern, args...) != cudaSuccess) {
        kern<<<grid, block>>>(args...);   // fallback: plain launch
    }
}

extern "C" void kernel_launch(void* const* d_in, const int* in_sizes, int n_in,
                              void* d_out, int out_size) {
    const float* x     = (const float*)d_in[0];
    const int*   ei    = (const int*)  d_in[1];
    const float* ea    = (const float*)d_in[2];
    const float* ins   = (const float*)d_in[3];
    const int*   batch = (const int*)  d_in[4];
    const float* Wl    = (const float*)d_in[5];
    const float* We    = (const float*)d_in[6];
    const float* attl  = (const float*)d_in[7];
    const float* attr_ = (const float*)d_in[8];
    const float* atte  = (const float*)d_in[9];
    const float* bias  = (const float*)d_in[10];
    const float* gamma = (const float*)d_in[11];
    const float* beta  = (const float*)d_in[12];
    float* out = (float*)d_out;

    pdl(prep_weights, dim3(6), dim3(256), Wl, We, attl, attr_, atte);
    pdl(prep_ins, dim3(EE / 256), dim3(256), ins, Wl, ei);
    pdl(scan_kernel, dim3(1), dim3(1024));
    pdl(place_kernel, dim3(EE / 256), dim3(256), ei);
    pdl(sort_kernel, dim3(NN / 8), dim3(256));
    pdl(edge_pre, dim3(EE / 8), dim3(256), ei, ea, batch);

    pdl(node_kernel, dim3(NN / 16), dim3(128), x, batch, Wl, beta, 0, 1, 0);
    pdl(gather_kernel, dim3(NN / 8), dim3(256), x, bias, beta, out, ei, 0, 1, 0, 1);
    pdl(bn_stats, dim3(BN_BLOCKS), dim3(256));
    pdl(bn_finalize, dim3(1), dim3(64), gamma);
    pdl(node_kernel, dim3(NN / 16), dim3(128), x, batch, Wl, beta, 1, 0, 1);
    pdl(gather_kernel, dim3(NN / 8), dim3(256), x, bias, beta, out, ei, 1, 0, 1, 0);
}

// round 16
// speedup vs baseline: 1.2025x; 1.2025x over previous
#include <cuda_runtime.h>
#include <cuda_bf16.h>

#define NN    20000
#define EE    320000
#define BB    128
#define DIN   64
#define HH    2
#define CC    64
#define LL    2
#define SLOPE 0.2f
#define EPSBN 1e-5f
#define BN_BLOCKS 100
#define SCAN_B 79   // ceil(NN/256)

// ---------------- scratch (device globals; no allocation) ----------------
__device__ float g_xl[NN * 128];            // [N][128] node features (both heads)
__device__ float g_al[NN * HH];
__device__ float g_ar[NN * HH];
__device__ float g_pe[LL * EE * HH];        // ae dot + ins term, both layers
__device__ float g_h[NN * DIN];             // hidden state between layers (pre-BN)
__device__ float g_wa[LL * 3 * 128 * HH];   // folded att vectors [l][{al,ar,ae}][k][h]
__device__ float g_ins_xl[LL * BB * 128];   // ins @ W_l_bottom
__device__ float g_ins_a[LL * 3 * BB * HH]; // ins @ w_{al,ar,ae}_bottom
__device__ int   g_cnt[NN];                 // in-degree histogram
__device__ int   g_start[NN + 1];           // CSR row starts
__device__ int   g_cur[NN];                 // placement cursors
__device__ int   g_csr[EE];                 // edge ids grouped by dst (sorted per bucket)
__device__ int   g_bsum[SCAN_B];            // scan block partials
__device__ float g_bnp[BN_BLOCKS * 64];
__device__ float g_bnp2[BN_BLOCKS * 64];
__device__ float g_mu[64];
__device__ float g_scale[64];               // gamma * rsqrt(var + eps)

// ---------------- prep 1: fold att vectors through W; zero histogram ----------------
__global__ void prep_weights(const float* __restrict__ Wl, const float* __restrict__ We,
                             const float* __restrict__ attl, const float* __restrict__ attr_,
                             const float* __restrict__ atte) {
    int idx = blockIdx.x * blockDim.x + threadIdx.x;
    if (idx < NN) g_cnt[idx] = 0;
    if (idx >= LL * 3 * 128 * HH) return;
    int l  = idx / (3 * 128 * HH);
    int r  = idx % (3 * 128 * HH);
    int t  = r / (128 * HH);
    int r2 = r % (128 * HH);
    int k  = r2 / HH;
    int h  = r2 % HH;
    const float* W   = (t == 2) ? We : Wl;
    const float* att = (t == 0) ? attl : (t == 1) ? attr_ : atte;
    float acc = 0.f;
#pragma unroll 8
    for (int c = 0; c < CC; c++)
        acc += W[l * 128 * 128 + k * 128 + h * CC + c] * att[l * HH * CC + h * CC + c];
    g_wa[((l * 3 + t) * 128 + k) * HH + h] = acc;
}

// ---------------- prep 2: per-graph instruction terms + dst histogram ----------------
__global__ void prep_ins(const float* __restrict__ ins, const float* __restrict__ Wl,
                         const int* __restrict__ ei) {
    int idx = blockIdx.x * blockDim.x + threadIdx.x;
    const int NXL = LL * BB * 128;
    if (idx < NXL) {
        int l = idx / (BB * 128);
        int r = idx % (BB * 128);
        int b = r / 128;
        int m = r % 128;
        float acc = 0.f;
#pragma unroll 8
        for (int k = 0; k < DIN; k++)
            acc += ins[(l * BB + b) * DIN + k] * Wl[l * 128 * 128 + (64 + k) * 128 + m];
        g_ins_xl[(l * BB + b) * 128 + m] = acc;
    } else if (idx < NXL + LL * 3 * BB * HH) {
        int j  = idx - NXL;
        int l  = j / (3 * BB * HH);
        int r  = j % (3 * BB * HH);
        int t  = r / (BB * HH);
        int r2 = r % (BB * HH);
        int b  = r2 / HH;
        int h  = r2 % HH;
        float acc = 0.f;
#pragma unroll 8
        for (int k = 0; k < DIN; k++)
            acc += ins[(l * BB + b) * DIN + k] * g_wa[((l * 3 + t) * 128 + 64 + k) * HH + h];
        g_ins_a[((l * 3 + t) * BB + b) * HH + h] = acc;
    }
    if (idx < EE) atomicAdd(&g_cnt[ei[EE + idx]], 1);
}

// ---------------- scan phase A: per-block sums ----------------
__global__ __launch_bounds__(256) void scanA() {
    __shared__ int sh[256];
    int t = threadIdx.x;
    int n = blockIdx.x * 256 + t;
    sh[t] = (n < NN) ? g_cnt[n] : 0;
    __syncthreads();
#pragma unroll
    for (int off = 128; off; off >>= 1) {
        if (t < off) sh[t] += sh[t + off];
        __syncthreads();
    }
    if (t == 0) g_bsum[blockIdx.x] = sh[0];
}

// ---------------- scan phase C: block offset (inline) + intra-block scan ----------------
__global__ __launch_bounds__(256) void scanC() {
    __shared__ int sh[256];
    __shared__ int soff;
    int t = threadIdx.x;
    int n = blockIdx.x * 256 + t;
    int v = (n < NN) ? g_cnt[n] : 0;
    if (t < 32) {   // warp 0: offset = sum of preceding block sums
        int off = 0;
        for (int j = t; j < (int)blockIdx.x; j += 32) off += g_bsum[j];
#pragma unroll
        for (int o = 16; o; o >>= 1) off += __shfl_xor_sync(0xffffffffu, off, o);
        if (t == 0) soff = off;
    }
    sh[t] = v;
    __syncthreads();
    for (int off = 1; off < 256; off <<= 1) {
        int u = (t >= off) ? sh[t - off] : 0;
        __syncthreads();
        sh[t] += u;
        __syncthreads();
    }
    if (n < NN) {
        int start = soff + sh[t] - v;   // exclusive within block
        g_start[n] = start;
        g_cur[n] = start;
        if (n == NN - 1) g_start[NN] = start + v;
    }
}

__global__ void place_kernel(const int* __restrict__ ei) {
    int e = blockIdx.x * blockDim.x + threadIdx.x;
    if (e >= EE) return;
    int d = ei[EE + e];
    int pos = atomicAdd(&g_cur[d], 1);
    g_csr[pos] = e;
}

// ---------------- canonicalize bucket order: warp rank sort ----------------
__global__ __launch_bounds__(256) void sort_kernel() {
    int warp = threadIdx.x >> 5, lane = threadIdx.x & 31;
    int n = blockIdx.x * 8 + warp;
    if (n >= NN) return;
    int s0 = g_start[n], s1 = g_start[n + 1];
    int d = s1 - s0;
    if (d <= 1) return;
    if (d <= 32) {
        int v = (lane < d) ? g_csr[s0 + lane] : 0x7fffffff;
        int rank = 0;
#pragma unroll
        for (int j = 0; j < 32; j++) {
            int u = __shfl_sync(0xffffffffu, v, j);
            rank += (u < v);
        }
        __syncwarp();
        if (lane < d) g_csr[s0 + rank] = v;
    } else if (lane == 0) {
        for (int i = s0 + 1; i < s1; i++) {
            int v = g_csr[i];
            int j = i - 1;
            while (j >= s0 && g_csr[j] > v) { g_csr[j + 1] = g_csr[j]; j--; }
            g_csr[j + 1] = v;
        }
    }
}

// ---------------- edge precompute (ONCE): ae dots + ins terms, both layers ----------------
__global__ __launch_bounds__(256) void edge_pre(
    const int* __restrict__ ei, const float* __restrict__ ea,
    const int* __restrict__ batch) {
    int warp = threadIdx.x >> 5, lane = threadIdx.x & 31;
    int e = blockIdx.x * 8 + warp;
    float ea0 = ea[e * 64 + lane];
    float ea1 = ea[e * 64 + 32 + lane];
    float p[LL][HH];
#pragma unroll
    for (int l = 0; l < LL; l++) {
        const float* w = &g_wa[((l * 3 + 2) * 128) * HH];
#pragma unroll
        for (int h = 0; h < HH; h++)
            p[l][h] = ea0 * w[lane * 2 + h] + ea1 * w[(lane + 32) * 2 + h];
    }
#pragma unroll
    for (int off = 16; off; off >>= 1)
#pragma unroll
        for (int l = 0; l < LL; l++)
#pragma unroll
            for (int h = 0; h < HH; h++)
                p[l][h] += __shfl_xor_sync(0xffffffffu, p[l][h], off);
    if (lane == 0) {
        int s = ei[e];
        int b = batch[s];
#pragma unroll
        for (int l = 0; l < LL; l++) {
            float2 v;
            v.x = p[l][0] + g_ins_a[((l * 3 + 2) * BB + b) * HH + 0];
            v.y = p[l][1] + g_ins_a[((l * 3 + 2) * BB + b) * HH + 1];
            *(float2*)&g_pe[(l * EE + e) * 2] = v;
        }
    }
}

// ---------------- node kernel: xl, al, ar (optional fused BN+relu on input) ----------------
__global__ __launch_bounds__(128) void node_kernel(
    const float* __restrict__ x, const int* __restrict__ batch,
    const float* __restrict__ Wl, const float* __restrict__ beta,
    int l, int use_x, int bn_in) {
    __shared__ __align__(16) float hs[64][16];   // [k][n]
    __shared__ int bsm[16];
    const float* hin = use_x ? x : g_h;
    int node0 = blockIdx.x * 16;
    int t = threadIdx.x;
#pragma unroll
    for (int i = t; i < 16 * 64; i += 128) {
        int n = i >> 6, k = i & 63;
        float v = hin[(node0 + n) * DIN + k];
        if (bn_in) {
            v = (v - g_mu[k]) * g_scale[k] + beta[k];
            v = v > 0.f ? v : 0.f;
        }
        hs[k][n] = v;
    }
    if (t < 16) bsm[t] = batch[node0 + t];
    __syncthreads();

    int m = t;  // output column 0..127
    float acc[16];
#pragma unroll
    for (int n = 0; n < 16; n++)
        acc[n] = g_ins_xl[(l * BB + bsm[n]) * 128 + m];

    const float* Wtop = Wl + l * 128 * 128;
#pragma unroll 4
    for (int k = 0; k < 64; k++) {
        float w = Wtop[k * 128 + m];
        float4 a = *(const float4*)&hs[k][0];
        float4 b = *(const float4*)&hs[k][4];
        float4 c = *(const float4*)&hs[k][8];
        float4 d = *(const float4*)&hs[k][12];
        acc[0]  += a.x * w; acc[1]  += a.y * w; acc[2]  += a.z * w; acc[3]  += a.w * w;
        acc[4]  += b.x * w; acc[5]  += b.y * w; acc[6]  += b.z * w; acc[7]  += b.w * w;
        acc[8]  += c.x * w; acc[9]  += c.y * w; acc[10] += c.z * w; acc[11] += c.w * w;
        acc[12] += d.x * w; acc[13] += d.y * w; acc[14] += d.z * w; acc[15] += d.w * w;
    }
#pragma unroll
    for (int n = 0; n < 16; n++)
        g_xl[(node0 + n) * 128 + m] = acc[n];

    if (t < 64) {
        int n  = t >> 2;
        int q  = t & 3;
        int ta = q >> 1;
        int hh = q & 1;
        float a2 = 0.f;
        const float* w = &g_wa[((l * 3 + ta) * 128) * HH + hh];
#pragma unroll 8
        for (int k = 0; k < 64; k++)
            a2 += hs[k][n] * w[k * HH];
        a2 += g_ins_a[((l * 3 + ta) * BB + bsm[n]) * HH + hh];
        float* dst = (ta == 0) ? g_al : g_ar;
        dst[(node0 + n) * HH + hh] = a2;
    }
}

// =================================================================
// gather: 256 thr = 8 warps = 8 nodes/block; fused logit+exp+softmax+agg
// =================================================================
__global__ __launch_bounds__(256) void gather_kernel(
    const float* __restrict__ x, const float* __restrict__ bias,
    const float* __restrict__ beta, float* __restrict__ dout,
    const int* __restrict__ ei, int l, int use_x, int bn_in, int do_bn_out) {
    int warp = threadIdx.x >> 5, lane = threadIdx.x & 31;
    int n = blockIdx.x * 8 + warp;
    const float* hin = use_x ? x : g_h;
    float* hout = do_bn_out ? g_h : dout;
    int s0 = g_start[n], s1 = g_start[n + 1];
    float2 arn = *(const float2*)&g_ar[n * 2];

    // chunk 0 (covers all edges when deg <= 32): per-lane logit -> exp
    int i = s0 + lane;
    int src = 0;
    float ex0 = 0.f, ex1 = 0.f;
    if (i < s1) {
        int e = g_csr[i];
        src = ei[e];
        float2 pe = *(const float2*)&g_pe[(l * EE + e) * 2];
        float2 al2 = *(const float2*)&g_al[src * 2];
        float a0 = pe.x + al2.x + arn.x;
        float a1 = pe.y + al2.y + arn.y;
        a0 = a0 > 0.f ? a0 : SLOPE * a0;
        a1 = a1 > 0.f ? a1 : SLOPE * a1;
        ex0 = __expf(a0);
        ex1 = __expf(a1);
    }
    float ss0 = ex0, ss1 = ex1;
    for (int base = s0 + 32; base < s1; base += 32) {   // rare (deg > 32)
        int j = base + lane;
        if (j < s1) {
            int e = g_csr[j];
            int sj = ei[e];
            float2 pe = *(const float2*)&g_pe[(l * EE + e) * 2];
            float2 al2 = *(const float2*)&g_al[sj * 2];
            float a0 = pe.x + al2.x + arn.x;
            float a1 = pe.y + al2.y + arn.y;
            a0 = a0 > 0.f ? a0 : SLOPE * a0;
            a1 = a1 > 0.f ? a1 : SLOPE * a1;
            ss0 += __expf(a0);
            ss1 += __expf(a1);
        }
    }
#pragma unroll
    for (int off = 16; off; off >>= 1) {
        ss0 += __shfl_xor_sync(0xffffffffu, ss0, off);
        ss1 += __shfl_xor_sync(0xffffffffu, ss1, off);
    }
    float inv0 = 0.5f / (ss0 + 1e-16f);
    float inv1 = 0.5f / (ss1 + 1e-16f);

    // accumulate: lane reads one float4 of the 128-float source row.
    // lanes 0-15 cover head0 (cols 0..63), lanes 16-31 head1 (cols 64..127).
    float4 acc = make_float4(0.f, 0.f, 0.f, 0.f);
    bool head0 = (lane < 16);
    int dc = s1 - s0; if (dc > 32) dc = 32;
    for (int k = 0; k < dc; k++) {
        float w0 = __shfl_sync(0xffffffffu, ex0, k) * inv0;
        float w1 = __shfl_sync(0xffffffffu, ex1, k) * inv1;
        int sj   = __shfl_sync(0xffffffffu, src, k);
        float w = head0 ? w0 : w1;
        float4 v = ((const float4*)(g_xl + sj * 128))[lane];
        acc.x += w * v.x; acc.y += w * v.y; acc.z += w * v.z; acc.w += w * v.w;
    }
    // rare tail: recompute ex per chunk (deterministic), then accumulate
    for (int base = s0 + 32; base < s1; base += 32) {
        int j = base + lane;
        int src2 = 0;
        float e0 = 0.f, e1 = 0.f;
        if (j < s1) {
            int e = g_csr[j];
            src2 = ei[e];
            float2 pe = *(const float2*)&g_pe[(l * EE + e) * 2];
            float2 al2 = *(const float2*)&g_al[src2 * 2];
            float a0 = pe.x + al2.x + arn.x;
            float a1 = pe.y + al2.y + arn.y;
            a0 = a0 > 0.f ? a0 : SLOPE * a0;
            a1 = a1 > 0.f ? a1 : SLOPE * a1;
            e0 = __expf(a0);
            e1 = __expf(a1);
        }
        int cnt = s1 - base; if (cnt > 32) cnt = 32;
        for (int k = 0; k < cnt; k++) {
            float w0 = __shfl_sync(0xffffffffu, e0, k) * inv0;
            float w1 = __shfl_sync(0xffffffffu, e1, k) * inv1;
            int sj   = __shfl_sync(0xffffffffu, src2, k);
            float w = head0 ? w0 : w1;
            float4 v = ((const float4*)(g_xl + sj * 128))[lane];
            acc.x += w * v.x; acc.y += w * v.y; acc.z += w * v.z; acc.w += w * v.w;
        }
    }

    // head mean: lane L (head0 part) + lane L+16 (head1 part) -> channels 4L..4L+3
    acc.x += __shfl_down_sync(0xffffffffu, acc.x, 16);
    acc.y += __shfl_down_sync(0xffffffffu, acc.y, 16);
    acc.z += __shfl_down_sync(0xffffffffu, acc.z, 16);
    acc.w += __shfl_down_sync(0xffffffffu, acc.w, 16);

    if (lane < 16) {
        float4 h4 = ((const float4*)(hin + n * DIN))[lane];
        if (bn_in) {
            float4 mu = ((const float4*)g_mu)[lane];
            float4 sc = ((const float4*)g_scale)[lane];
            float4 be = ((const float4*)beta)[lane];
            h4.x = (h4.x - mu.x) * sc.x + be.x; h4.x = h4.x > 0.f ? h4.x : 0.f;
            h4.y = (h4.y - mu.y) * sc.y + be.y; h4.y = h4.y > 0.f ? h4.y : 0.f;
            h4.z = (h4.z - mu.z) * sc.z + be.z; h4.z = h4.z > 0.f ? h4.z : 0.f;
            h4.w = (h4.w - mu.w) * sc.w + be.w; h4.w = h4.w > 0.f ? h4.w : 0.f;
        }
        float4 b4 = ((const float4*)(bias + l * CC))[lane];
        float4 o;
        o.x = acc.x + b4.x + h4.x;
        o.y = acc.y + b4.y + h4.y;
        o.z = acc.z + b4.z + h4.z;
        o.w = acc.w + b4.w + h4.w;
        ((float4*)(hout + n * DIN))[lane] = o;
    }
}

// ---------------- BN stats (deterministic two-stage) ----------------
__global__ __launch_bounds__(256) void bn_stats() {
    __shared__ float s1[256], s2m[256];
    int t = threadIdx.x;
    int c = t & 63, slot = t >> 6;
    float su = 0.f, sq = 0.f;
    for (int n = blockIdx.x * 4 + slot; n < NN; n += BN_BLOCKS * 4) {
        float v = g_h[n * DIN + c];
        su += v;
        sq += v * v;
    }
    s1[t] = su; s2m[t] = sq;
    __syncthreads();
    if (t < 64) {
        g_bnp[blockIdx.x * 64 + t]  = s1[t] + s1[t + 64] + s1[t + 128] + s1[t + 192];
        g_bnp2[blockIdx.x * 64 + t] = s2m[t] + s2m[t + 64] + s2m[t + 128] + s2m[t + 192];
    }
}

__global__ void bn_finalize(const float* __restrict__ gamma) {
    int c = threadIdx.x;
    if (c >= 64) return;
    float su = 0.f, sq = 0.f;
    for (int b = 0; b < BN_BLOCKS; b++) {
        su += g_bnp[b * 64 + c];
        sq += g_bnp2[b * 64 + c];
    }
    float mu = su / (float)NN;
    float var = sq / (float)NN - mu * mu;
    g_mu[c] = mu;
    g_scale[c] = gamma[c] * rsqrtf(var + EPSBN);
}

extern "C" void kernel_launch(void* const* d_in, const int* in_sizes, int n_in,
                              void* d_out, int out_size) {
    const float* x     = (const float*)d_in[0];
    const int*   ei    = (const int*)  d_in[1];
    const float* ea    = (const float*)d_in[2];
    const float* ins   = (const float*)d_in[3];
    const int*   batch = (const int*)  d_in[4];
    const float* Wl    = (const float*)d_in[5];
    const float* We    = (const float*)d_in[6];
    const float* attl  = (const float*)d_in[7];
    const float* attr_ = (const float*)d_in[8];
    const float* atte  = (const float*)d_in[9];
    const float* bias  = (const float*)d_in[10];
    const float* gamma = (const float*)d_in[11];
    const float* beta  = (const float*)d_in[12];
    float* out = (float*)d_out;

    // Fork/join: CSR build runs on a side stream, overlapped with
    // edge_pre + node0 on the main stream. Created fresh each call
    // (kernel_launch runs only for correctness + capture), so the
    // enqueued work is identical on every call.
    cudaStream_t s1;
    cudaEvent_t evPrep, evCSR;
    bool forked =
        (cudaStreamCreateWithFlags(&s1, cudaStreamNonBlocking) == cudaSuccess) &&
        (cudaEventCreateWithFlags(&evPrep, cudaEventDisableTiming) == cudaSuccess) &&
        (cudaEventCreateWithFlags(&evCSR, cudaEventDisableTiming) == cudaSuccess);

    prep_weights<<<SCAN_B, 256>>>(Wl, We, attl, attr_, atte);          // + zero cnt
    prep_ins<<<EE / 256, 256>>>(ins, Wl, ei);                          // + histogram

    if (forked) {
        cudaEventRecord(evPrep, 0);
        cudaStreamWaitEvent(s1, evPrep, 0);
        scanA<<<SCAN_B, 256, 0, s1>>>();
        scanC<<<SCAN_B, 256, 0, s1>>>();
        place_kernel<<<EE / 256, 256, 0, s1>>>(ei);
        sort_kernel<<<NN / 8, 256, 0, s1>>>();
        cudaEventRecord(evCSR, s1);
        // main stream: independent of CSR
        edge_pre<<<EE / 8, 256>>>(ei, ea, batch);
        node_kernel<<<NN / 16, 128>>>(x, batch, Wl, beta, 0, 1, 0);
        cudaStreamWaitEvent(0, evCSR, 0);                               // join
    } else {
        scanA<<<SCAN_B, 256>>>();
        scanC<<<SCAN_B, 256>>>();
        place_kernel<<<EE / 256, 256>>>(ei);
        sort_kernel<<<NN / 8, 256>>>();
        edge_pre<<<EE / 8, 256>>>(ei, ea, batch);
        node_kernel<<<NN / 16, 128>>>(x, batch, Wl, beta, 0, 1, 0);
    }

    gather_kernel<<<NN / 8, 256>>>(x, bias, beta, out, ei, 0, 1, 0, 1); // -> g_h
    bn_stats<<<BN_BLOCKS, 256>>>();
    bn_finalize<<<1, 64>>>(gamma);
    node_kernel<<<NN / 16, 128>>>(x, batch, Wl, beta, 1, 0, 1);
    gather_kernel<<<NN / 8, 256>>>(x, bias, beta, out, ei, 1, 0, 1, 0); // -> out
}